// round 2
// baseline (speedup 1.0000x reference)
#include <cuda_runtime.h>
#include <math.h>

#define BATCH   2
#define LSEQ    2048
#define MTOK    (BATCH*LSEQ)          // 4096
#define DMODEL  2048
#define DINNER  2048
#define NH      32
#define DSTATE  64
#define HD      64
#define CHUNK   128
#define NCHUNK  (LSEQ/CHUNK)          // 16
#define DFF     8192
#define CONVD   (DINNER + 2*NH*DSTATE)          // 6144
#define DINPROJ (2*DINNER + 2*NH*DSTATE + NH)   // 8224
#define DTOFF   (DINNER + CONVD)                // 8192

// ------------------------- scratch (device globals, no allocs) -------------
__device__ float g_h1  [(size_t)MTOK*DMODEL];
__device__ float g_zx  [(size_t)MTOK*DINPROJ];
__device__ float g_xBC [(size_t)MTOK*CONVD];
__device__ float g_y   [(size_t)MTOK*DINNER];
__device__ float g_S   [(size_t)BATCH*NCHUNK*NH*DSTATE*HD];
__device__ float g_Ac  [(size_t)BATCH*NCHUNK*NH];
__device__ float g_cum [(size_t)BATCH*NCHUNK*NH*CHUNK];
__device__ float g_Hp  [(size_t)BATCH*NCHUNK*NH*DSTATE*HD];
__device__ float g_h2  [(size_t)MTOK*DMODEL];
__device__ float g_h3  [(size_t)MTOK*DMODEL];
__device__ float g_gate[(size_t)MTOK*DFF];
__device__ float g_up  [(size_t)MTOK*DFF];

// ------------------------------ rmsnorm ------------------------------------
__global__ void rmsnorm_kernel(const float* __restrict__ x, const float* __restrict__ w,
                               float* __restrict__ y) {
    int row = blockIdx.x;
    const float* xr = x + (size_t)row * DMODEL;
    float ss = 0.f;
    for (int c = threadIdx.x; c < DMODEL; c += 256) { float v = xr[c]; ss += v * v; }
    #pragma unroll
    for (int off = 16; off; off >>= 1) ss += __shfl_xor_sync(0xffffffffu, ss, off);
    __shared__ float red[8];
    if ((threadIdx.x & 31) == 0) red[threadIdx.x >> 5] = ss;
    __syncthreads();
    if (threadIdx.x < 8) {
        float v = red[threadIdx.x];
        #pragma unroll
        for (int off = 4; off; off >>= 1) v += __shfl_xor_sync(0xffu, v, off);
        if (threadIdx.x == 0) red[0] = v;
    }
    __syncthreads();
    float inv = rsqrtf(red[0] / (float)DMODEL + 1e-5f);
    float* yr = y + (size_t)row * DMODEL;
    for (int c = threadIdx.x; c < DMODEL; c += 256) yr[c] = w[c] * xr[c] * inv;
}

// ------------------------------ SGEMM (C = A * W^T [+ res]) ----------------
// A: [M,K] row-major, W: [N,K] row-major, C: [M,N]. 128x128 tile, BK=16,
// 256 threads, 8x8 per thread. M % 128 == 0, K % 16 == 0, N guarded.
__global__ void sgemm_nt_kernel(const float* __restrict__ A, const float* __restrict__ W,
                                const float* __restrict__ res, float* __restrict__ C,
                                int M, int N, int K) {
    __shared__ float As[16][129];
    __shared__ float Ws[16][129];
    int tid = threadIdx.x;
    int bm = blockIdx.y * 128, bn = blockIdx.x * 128;
    int ty = tid >> 4, tx = tid & 15;
    int lr = tid >> 2;            // 0..63
    int lc = (tid & 3) * 4;       // 0,4,8,12

    float acc[8][8];
    #pragma unroll
    for (int r = 0; r < 8; r++)
        #pragma unroll
        for (int s = 0; s < 8; s++) acc[r][s] = 0.f;

    for (int k0 = 0; k0 < K; k0 += 16) {
        #pragma unroll
        for (int pass = 0; pass < 2; pass++) {
            int r = lr + pass * 64;
            float4 av = *(const float4*)(A + (size_t)(bm + r) * K + k0 + lc);
            As[lc + 0][r] = av.x; As[lc + 1][r] = av.y;
            As[lc + 2][r] = av.z; As[lc + 3][r] = av.w;
            int n = bn + r;
            float4 wv = make_float4(0.f, 0.f, 0.f, 0.f);
            if (n < N) wv = *(const float4*)(W + (size_t)n * K + k0 + lc);
            Ws[lc + 0][r] = wv.x; Ws[lc + 1][r] = wv.y;
            Ws[lc + 2][r] = wv.z; Ws[lc + 3][r] = wv.w;
        }
        __syncthreads();
        #pragma unroll
        for (int kk = 0; kk < 16; kk++) {
            float af[8], bf[8];
            #pragma unroll
            for (int r = 0; r < 8; r++) af[r] = As[kk][ty * 8 + r];
            #pragma unroll
            for (int s = 0; s < 8; s++) bf[s] = Ws[kk][tx * 8 + s];
            #pragma unroll
            for (int r = 0; r < 8; r++)
                #pragma unroll
                for (int s = 0; s < 8; s++) acc[r][s] += af[r] * bf[s];
        }
        __syncthreads();
    }
    #pragma unroll
    for (int r = 0; r < 8; r++) {
        int m = bm + ty * 8 + r;
        #pragma unroll
        for (int s = 0; s < 8; s++) {
            int n = bn + tx * 8 + s;
            if (n < N) {
                float v = acc[r][s];
                if (res) v += res[(size_t)m * N + n];
                C[(size_t)m * N + n] = v;
            }
        }
    }
}

// ------------------------------ causal depthwise conv ----------------------
__global__ void conv1d_kernel(const float* __restrict__ zx, const float* __restrict__ cw,
                              const float* __restrict__ cb, float* __restrict__ xBC) {
    size_t idx = (size_t)blockIdx.x * blockDim.x + threadIdx.x;
    if (idx >= (size_t)MTOK * CONVD) return;
    int c = (int)(idx % CONVD);
    int m = (int)(idx / CONVD);
    int t = m & (LSEQ - 1);           // position within sequence
    float acc = cb[c];
    #pragma unroll
    for (int j = 0; j < 4; j++) {
        int tt = t - 3 + j;
        if (tt >= 0)
            acc += cw[c * 4 + j] * zx[(size_t)(m - 3 + j) * DINPROJ + DINNER + c];
    }
    xBC[idx] = acc;
}

// ------------------------------ SSD intra-chunk ----------------------------
// one block per (b, chunk, head). Computes y_intra, chunk state S, A_chunk, cum.
__global__ void ssd_intra_kernel(const float* __restrict__ zx, const float* __restrict__ xBC,
                                 float* __restrict__ y, float* __restrict__ Sg,
                                 float* __restrict__ Ag, float* __restrict__ cumg) {
    extern __shared__ float sm[];
    float* xs   = sm;                       // 128*65
    float* Bs   = xs + CHUNK * 65;          // 128*65
    float* Cs   = Bs + CHUNK * 65;          // 128*65
    float* sc   = Cs + CHUNK * 65;          // 128*129
    float* cum  = sc + CHUNK * 129;         // 128
    float* dend = cum + CHUNK;              // 128

    int h = blockIdx.x % NH;
    int c = (blockIdx.x / NH) % NCHUNK;
    int b = blockIdx.x / (NH * NCHUNK);
    int tid = threadIdx.x;
    int m0 = b * LSEQ + c * CHUNK;

    for (int idx = tid; idx < CHUNK * HD; idx += 256) {
        int i = idx >> 6, p = idx & 63;
        size_t rowb = (size_t)(m0 + i) * CONVD;
        xs[i * 65 + p] = xBC[rowb + h * HD + p];
        Bs[i * 65 + p] = xBC[rowb + DINNER + h * DSTATE + p];
        Cs[i * 65 + p] = xBC[rowb + DINNER + NH * DSTATE + h * DSTATE + p];
    }
    if (tid < CHUNK) {
        float d = zx[(size_t)(m0 + tid) * DINPROJ + DTOFF + h];
        float sp = (d > 20.f) ? d : log1pf(expf(d));
        cum[tid] = -sp;
    }
    __syncthreads();
    // inclusive scan (Hillis-Steele)
    for (int off = 1; off < CHUNK; off <<= 1) {
        float v = 0.f;
        if (tid < CHUNK && tid >= off) v = cum[tid - off];
        __syncthreads();
        if (tid < CHUNK && tid >= off) cum[tid] += v;
        __syncthreads();
    }
    if (tid < CHUNK) dend[tid] = expf(cum[CHUNK - 1] - cum[tid]);
    __syncthreads();

    int ty = tid >> 4, tx = tid & 15;
    // Phase A: masked decayed scores sc[i][j] = exp(cum_i - cum_j) * dot(C_i, B_j)
    {
        float acc[8][8];
        #pragma unroll
        for (int r = 0; r < 8; r++)
            #pragma unroll
            for (int s = 0; s < 8; s++) acc[r][s] = 0.f;
        int i0 = ty * 8;
        for (int n = 0; n < DSTATE; n++) {
            float cf[8], bf[8];
            #pragma unroll
            for (int r = 0; r < 8; r++) cf[r] = Cs[(i0 + r) * 65 + n];
            #pragma unroll
            for (int s = 0; s < 8; s++) bf[s] = Bs[(tx + 16 * s) * 65 + n];
            #pragma unroll
            for (int r = 0; r < 8; r++)
                #pragma unroll
                for (int s = 0; s < 8; s++) acc[r][s] += cf[r] * bf[s];
        }
        #pragma unroll
        for (int r = 0; r < 8; r++) {
            int i = i0 + r;
            float ci = cum[i];
            #pragma unroll
            for (int s = 0; s < 8; s++) {
                int j = tx + 16 * s;
                sc[i * 129 + j] = (j <= i) ? expf(ci - cum[j]) * acc[r][s] : 0.f;
            }
        }
    }
    __syncthreads();
    // Phase B: y_intra = sc @ x
    {
        float acc[8][4];
        #pragma unroll
        for (int r = 0; r < 8; r++)
            #pragma unroll
            for (int cc = 0; cc < 4; cc++) acc[r][cc] = 0.f;
        int i0 = ty * 8, p0 = tx * 4;
        for (int j = 0; j < CHUNK; j++) {
            float xv[4];
            #pragma unroll
            for (int cc = 0; cc < 4; cc++) xv[cc] = xs[j * 65 + p0 + cc];
            #pragma unroll
            for (int r = 0; r < 8; r++) {
                float sf = sc[(i0 + r) * 129 + j];
                #pragma unroll
                for (int cc = 0; cc < 4; cc++) acc[r][cc] += sf * xv[cc];
            }
        }
        #pragma unroll
        for (int r = 0; r < 8; r++) {
            size_t ybase = (size_t)(m0 + i0 + r) * DINNER + h * HD + p0;
            #pragma unroll
            for (int cc = 0; cc < 4; cc++) y[ybase + cc] = acc[r][cc];
        }
    }
    // Phase C: chunk state S[n][p] = sum_j dend[j] * B[j,n] * x[j,p]
    {
        int n = tid >> 2;
        int p0 = (tid & 3) * 16;
        float acc[16];
        #pragma unroll
        for (int cc = 0; cc < 16; cc++) acc[cc] = 0.f;
        for (int j = 0; j < CHUNK; j++) {
            float w = dend[j] * Bs[j * 65 + n];
            #pragma unroll
            for (int cc = 0; cc < 16; cc++) acc[cc] += w * xs[j * 65 + p0 + cc];
        }
        size_t off = ((size_t)((b * NCHUNK + c) * NH + h)) * (DSTATE * HD) + n * HD + p0;
        #pragma unroll
        for (int cc = 0; cc < 16; cc++) Sg[off + cc] = acc[cc];
        if (tid == 0) Ag[(b * NCHUNK + c) * NH + h] = expf(cum[CHUNK - 1]);
    }
    if (tid < CHUNK)
        cumg[((size_t)((b * NCHUNK + c) * NH + h)) * CHUNK + tid] = cum[tid];
}

// ------------------------------ inter-chunk state recurrence ----------------
__global__ void state_scan_kernel(const float* __restrict__ Sg, const float* __restrict__ Ag,
                                  float* __restrict__ Hp) {
    int b = blockIdx.x / NH, h = blockIdx.x % NH;
    int tid = threadIdx.x;
    float H[16];
    #pragma unroll
    for (int k = 0; k < 16; k++) H[k] = 0.f;
    for (int c = 0; c < NCHUNK; c++) {
        size_t off = ((size_t)((b * NCHUNK + c) * NH + h)) * (DSTATE * HD);
        float Ac = Ag[(b * NCHUNK + c) * NH + h];
        #pragma unroll
        for (int k = 0; k < 16; k++) {
            int e = tid + k * 256;
            Hp[off + e] = H[k];
            H[k] = Ac * H[k] + Sg[off + e];
        }
    }
}

// ------------------------------ y_inter + D*x + gating ---------------------
__global__ void y_inter_kernel(const float* __restrict__ zx, const float* __restrict__ xBC,
                               const float* __restrict__ Hp, const float* __restrict__ cumg,
                               const float* __restrict__ Dvec, const float* __restrict__ zb,
                               float* __restrict__ y) {
    extern __shared__ float sm[];
    float* Cs  = sm;                  // 128*65
    float* xs  = Cs + CHUNK * 65;     // 128*65
    float* Hs  = xs + CHUNK * 65;     // 64*65
    float* cum = Hs + DSTATE * 65;    // 128

    int h = blockIdx.x % NH;
    int c = (blockIdx.x / NH) % NCHUNK;
    int b = blockIdx.x / (NH * NCHUNK);
    int tid = threadIdx.x;
    int m0 = b * LSEQ + c * CHUNK;
    size_t hoff = (size_t)((b * NCHUNK + c) * NH + h);

    for (int idx = tid; idx < CHUNK * HD; idx += 256) {
        int i = idx >> 6, p = idx & 63;
        size_t rowb = (size_t)(m0 + i) * CONVD;
        xs[i * 65 + p] = xBC[rowb + h * HD + p];
        Cs[i * 65 + p] = xBC[rowb + DINNER + NH * DSTATE + h * DSTATE + p];
    }
    for (int idx = tid; idx < DSTATE * HD; idx += 256)
        Hs[(idx >> 6) * 65 + (idx & 63)] = Hp[hoff * (DSTATE * HD) + idx];
    if (tid < CHUNK) cum[tid] = cumg[hoff * CHUNK + tid];
    __syncthreads();

    int i = tid >> 1;
    int p0 = (tid & 1) * 32;
    float acc[32];
    #pragma unroll
    for (int cc = 0; cc < 32; cc++) acc[cc] = 0.f;
    for (int n = 0; n < DSTATE; n++) {
        float cv = Cs[i * 65 + n];
        #pragma unroll
        for (int cc = 0; cc < 32; cc++) acc[cc] += cv * Hs[n * 65 + p0 + cc];
    }
    float e = expf(cum[i]);
    float Dh = Dvec[h];
    int m = m0 + i;
    size_t ybase = (size_t)m * DINNER + h * HD;
    size_t zbase = (size_t)m * DINPROJ + h * HD;
    #pragma unroll
    for (int cc = 0; cc < 32; cc++) {
        int p = p0 + cc;
        float yt = y[ybase + p] + e * acc[cc] + Dh * xs[i * 65 + p];
        float g = zx[zbase + p] + zb[h * HD + p];
        float sg = g / (1.f + expf(-g));
        y[ybase + p] = yt * sg;
    }
}

// ------------------------------ MLP elementwise -----------------------------
__global__ void silu_mul_kernel(float* __restrict__ gate, const float* __restrict__ up,
                                size_t n) {
    size_t i = (size_t)blockIdx.x * blockDim.x + threadIdx.x;
    if (i < n) {
        float g = gate[i];
        gate[i] = (g / (1.f + expf(-g))) * up[i];
    }
}

// ------------------------------ launch --------------------------------------
extern "C" void kernel_launch(void* const* d_in, const int* in_sizes, int n_in,
                              void* d_out, int out_size) {
    const float* hidden     = (const float*)d_in[0];
    const float* in_proj_w  = (const float*)d_in[1];
    const float* z_bias     = (const float*)d_in[2];
    const float* conv_w     = (const float*)d_in[3];
    const float* conv_b     = (const float*)d_in[4];
    const float* Dvec       = (const float*)d_in[5];
    const float* out_proj_w = (const float*)d_in[6];
    const float* norm1_w    = (const float*)d_in[7];
    const float* norm2_w    = (const float*)d_in[8];
    const float* gate_w     = (const float*)d_in[9];
    const float* up_w       = (const float*)d_in[10];
    const float* down_w     = (const float*)d_in[11];
    float* out = (float*)d_out;

    float *h1, *zx, *xbc, *y, *S, *A, *cumg, *Hp, *h2, *h3, *gate, *up;
    cudaGetSymbolAddress((void**)&h1,   g_h1);
    cudaGetSymbolAddress((void**)&zx,   g_zx);
    cudaGetSymbolAddress((void**)&xbc,  g_xBC);
    cudaGetSymbolAddress((void**)&y,    g_y);
    cudaGetSymbolAddress((void**)&S,    g_S);
    cudaGetSymbolAddress((void**)&A,    g_Ac);
    cudaGetSymbolAddress((void**)&cumg, g_cum);
    cudaGetSymbolAddress((void**)&Hp,   g_Hp);
    cudaGetSymbolAddress((void**)&h2,   g_h2);
    cudaGetSymbolAddress((void**)&h3,   g_h3);
    cudaGetSymbolAddress((void**)&gate, g_gate);
    cudaGetSymbolAddress((void**)&up,   g_up);

    const int SMEM_INTRA  = (3 * CHUNK * 65 + CHUNK * 129 + 2 * CHUNK) * sizeof(float);
    const int SMEM_YINTER = (2 * CHUNK * 65 + DSTATE * 65 + CHUNK) * sizeof(float);
    cudaFuncSetAttribute(ssd_intra_kernel, cudaFuncAttributeMaxDynamicSharedMemorySize, SMEM_INTRA);
    cudaFuncSetAttribute(y_inter_kernel,  cudaFuncAttributeMaxDynamicSharedMemorySize, SMEM_YINTER);

    // 1) rmsnorm 1
    rmsnorm_kernel<<<MTOK, 256>>>(hidden, norm1_w, h1);
    // 2) in_proj: zx = h1 @ in_proj_w^T   [4096 x 8224]
    sgemm_nt_kernel<<<dim3((DINPROJ + 127) / 128, MTOK / 128), 256>>>(
        h1, in_proj_w, nullptr, zx, MTOK, DINPROJ, DMODEL);
    // 3) causal depthwise conv over xBC slice
    conv1d_kernel<<<(int)(((size_t)MTOK * CONVD + 255) / 256), 256>>>(zx, conv_w, conv_b, xbc);
    // 4) SSD intra-chunk (y_intra, S, A, cum)
    ssd_intra_kernel<<<BATCH * NCHUNK * NH, 256, SMEM_INTRA>>>(zx, xbc, y, S, A, cumg);
    // 5) inter-chunk state recurrence
    state_scan_kernel<<<BATCH * NH, 256>>>(S, A, Hp);
    // 6) y_inter + D*x + silu(z) gating (in-place on y)
    y_inter_kernel<<<BATCH * NCHUNK * NH, 256, SMEM_YINTER>>>(zx, xbc, Hp, cumg, Dvec, z_bias, y);
    // 7) out_proj + residual: h2 = y @ out_proj_w^T + hidden
    sgemm_nt_kernel<<<dim3(DMODEL / 128, MTOK / 128), 256>>>(
        y, out_proj_w, hidden, h2, MTOK, DMODEL, DINNER);
    // 8) rmsnorm 2
    rmsnorm_kernel<<<MTOK, 256>>>(h2, norm2_w, h3);
    // 9) MLP gate / up
    sgemm_nt_kernel<<<dim3(DFF / 128, MTOK / 128), 256>>>(
        h3, gate_w, nullptr, gate, MTOK, DFF, DMODEL);
    sgemm_nt_kernel<<<dim3(DFF / 128, MTOK / 128), 256>>>(
        h3, up_w, nullptr, up, MTOK, DFF, DMODEL);
    // 10) act = silu(gate) * up (in-place on gate)
    silu_mul_kernel<<<(int)(((size_t)MTOK * DFF + 255) / 256), 256>>>(
        gate, up, (size_t)MTOK * DFF);
    // 11) down + residual: out = act @ down_w^T + h2
    sgemm_nt_kernel<<<dim3(DMODEL / 128, MTOK / 128), 256>>>(
        gate, down_w, h2, out, MTOK, DMODEL, DFF);
}

// round 3
// speedup vs baseline: 1.0003x; 1.0003x over previous
#include <cuda_runtime.h>
#include <math.h>

#define BATCH   2
#define LSEQ    2048
#define MTOK    (BATCH*LSEQ)          // 4096
#define DMODEL  2048
#define DINNER  2048
#define NH      32
#define DSTATE  64
#define HD      64
#define CHUNK   128
#define NCHUNK  (LSEQ/CHUNK)          // 16
#define DFF     8192
#define CONVD   (DINNER + 2*NH*DSTATE)          // 6144
#define DINPROJ (2*DINNER + 2*NH*DSTATE + NH)   // 8224
#define DTOFF   (DINNER + CONVD)                // 8192

// ------------------------- scratch (device globals, no allocs) -------------
__device__ float g_h1  [(size_t)MTOK*DMODEL];
__device__ float g_zx  [(size_t)MTOK*DINPROJ];
__device__ float g_xBC [(size_t)MTOK*CONVD];
__device__ float g_y   [(size_t)MTOK*DINNER];
__device__ float g_S   [(size_t)BATCH*NCHUNK*NH*DSTATE*HD];
__device__ float g_Ac  [(size_t)BATCH*NCHUNK*NH];
__device__ float g_cum [(size_t)BATCH*NCHUNK*NH*CHUNK];
__device__ float g_Hp  [(size_t)BATCH*NCHUNK*NH*DSTATE*HD];
__device__ float g_h2  [(size_t)MTOK*DMODEL];
__device__ float g_h3  [(size_t)MTOK*DMODEL];
__device__ float g_gate[(size_t)MTOK*DFF];
__device__ float g_up  [(size_t)MTOK*DFF];

// ------------------------------ rmsnorm ------------------------------------
__global__ void rmsnorm_kernel(const float* __restrict__ x, const float* __restrict__ w,
                               float* __restrict__ y) {
    int row = blockIdx.x;
    const float* xr = x + (size_t)row * DMODEL;
    float ss = 0.f;
    for (int c = threadIdx.x; c < DMODEL; c += 256) { float v = xr[c]; ss += v * v; }
    #pragma unroll
    for (int off = 16; off; off >>= 1) ss += __shfl_xor_sync(0xffffffffu, ss, off);
    __shared__ float red[8];
    if ((threadIdx.x & 31) == 0) red[threadIdx.x >> 5] = ss;
    __syncthreads();
    if (threadIdx.x < 8) {
        float v = red[threadIdx.x];
        #pragma unroll
        for (int off = 4; off; off >>= 1) v += __shfl_xor_sync(0xffu, v, off);
        if (threadIdx.x == 0) red[0] = v;
    }
    __syncthreads();
    float inv = rsqrtf(red[0] / (float)DMODEL + 1e-5f);
    float* yr = y + (size_t)row * DMODEL;
    for (int c = threadIdx.x; c < DMODEL; c += 256) yr[c] = w[c] * xr[c] * inv;
}

// ------------------------------ SGEMM (C = A * W^T [+ res]) ----------------
// A: [M,K] row-major, W: [N,K] row-major, C: [M,N]. 128x128 tile, BK=16,
// 256 threads, 8x8 per thread. M % 128 == 0, K % 16 == 0, N guarded.
__global__ void sgemm_nt_kernel(const float* __restrict__ A, const float* __restrict__ W,
                                const float* __restrict__ res, float* __restrict__ C,
                                int M, int N, int K) {
    __shared__ float As[16][129];
    __shared__ float Ws[16][129];
    int tid = threadIdx.x;
    int bm = blockIdx.y * 128, bn = blockIdx.x * 128;
    int ty = tid >> 4, tx = tid & 15;
    int lr = tid >> 2;            // 0..63
    int lc = (tid & 3) * 4;       // 0,4,8,12

    float acc[8][8];
    #pragma unroll
    for (int r = 0; r < 8; r++)
        #pragma unroll
        for (int s = 0; s < 8; s++) acc[r][s] = 0.f;

    for (int k0 = 0; k0 < K; k0 += 16) {
        #pragma unroll
        for (int pass = 0; pass < 2; pass++) {
            int r = lr + pass * 64;
            float4 av = *(const float4*)(A + (size_t)(bm + r) * K + k0 + lc);
            As[lc + 0][r] = av.x; As[lc + 1][r] = av.y;
            As[lc + 2][r] = av.z; As[lc + 3][r] = av.w;
            int n = bn + r;
            float4 wv = make_float4(0.f, 0.f, 0.f, 0.f);
            if (n < N) wv = *(const float4*)(W + (size_t)n * K + k0 + lc);
            Ws[lc + 0][r] = wv.x; Ws[lc + 1][r] = wv.y;
            Ws[lc + 2][r] = wv.z; Ws[lc + 3][r] = wv.w;
        }
        __syncthreads();
        #pragma unroll
        for (int kk = 0; kk < 16; kk++) {
            float af[8], bf[8];
            #pragma unroll
            for (int r = 0; r < 8; r++) af[r] = As[kk][ty * 8 + r];
            #pragma unroll
            for (int s = 0; s < 8; s++) bf[s] = Ws[kk][tx * 8 + s];
            #pragma unroll
            for (int r = 0; r < 8; r++)
                #pragma unroll
                for (int s = 0; s < 8; s++) acc[r][s] += af[r] * bf[s];
        }
        __syncthreads();
    }
    #pragma unroll
    for (int r = 0; r < 8; r++) {
        int m = bm + ty * 8 + r;
        #pragma unroll
        for (int s = 0; s < 8; s++) {
            int n = bn + tx * 8 + s;
            if (n < N) {
                float v = acc[r][s];
                if (res) v += res[(size_t)m * N + n];
                C[(size_t)m * N + n] = v;
            }
        }
    }
}

// ------------------------------ causal depthwise conv ----------------------
__global__ void conv1d_kernel(const float* __restrict__ zx, const float* __restrict__ cw,
                              const float* __restrict__ cb, float* __restrict__ xBC) {
    size_t idx = (size_t)blockIdx.x * blockDim.x + threadIdx.x;
    if (idx >= (size_t)MTOK * CONVD) return;
    int c = (int)(idx % CONVD);
    int m = (int)(idx / CONVD);
    int t = m & (LSEQ - 1);           // position within sequence
    float acc = cb[c];
    #pragma unroll
    for (int j = 0; j < 4; j++) {
        int tt = t - 3 + j;
        if (tt >= 0)
            acc += cw[c * 4 + j] * zx[(size_t)(m - 3 + j) * DINPROJ + DINNER + c];
    }
    xBC[idx] = acc;
}

// ------------------------------ SSD intra-chunk ----------------------------
// one block per (b, chunk, head). Computes y_intra, chunk state S, A_chunk, cum.
__global__ void ssd_intra_kernel(const float* __restrict__ zx, const float* __restrict__ xBC,
                                 float* __restrict__ y, float* __restrict__ Sg,
                                 float* __restrict__ Ag, float* __restrict__ cumg) {
    extern __shared__ float sm[];
    float* xs   = sm;                       // 128*65
    float* Bs   = xs + CHUNK * 65;          // 128*65
    float* Cs   = Bs + CHUNK * 65;          // 128*65
    float* sc   = Cs + CHUNK * 65;          // 128*129
    float* cum  = sc + CHUNK * 129;         // 128
    float* dend = cum + CHUNK;              // 128

    int h = blockIdx.x % NH;
    int c = (blockIdx.x / NH) % NCHUNK;
    int b = blockIdx.x / (NH * NCHUNK);
    int tid = threadIdx.x;
    int m0 = b * LSEQ + c * CHUNK;

    for (int idx = tid; idx < CHUNK * HD; idx += 256) {
        int i = idx >> 6, p = idx & 63;
        size_t rowb = (size_t)(m0 + i) * CONVD;
        xs[i * 65 + p] = xBC[rowb + h * HD + p];
        Bs[i * 65 + p] = xBC[rowb + DINNER + h * DSTATE + p];
        Cs[i * 65 + p] = xBC[rowb + DINNER + NH * DSTATE + h * DSTATE + p];
    }
    if (tid < CHUNK) {
        float d = zx[(size_t)(m0 + tid) * DINPROJ + DTOFF + h];
        float sp = (d > 20.f) ? d : log1pf(expf(d));
        cum[tid] = -sp;
    }
    __syncthreads();
    // inclusive scan (Hillis-Steele)
    for (int off = 1; off < CHUNK; off <<= 1) {
        float v = 0.f;
        if (tid < CHUNK && tid >= off) v = cum[tid - off];
        __syncthreads();
        if (tid < CHUNK && tid >= off) cum[tid] += v;
        __syncthreads();
    }
    if (tid < CHUNK) dend[tid] = expf(cum[CHUNK - 1] - cum[tid]);
    __syncthreads();

    int ty = tid >> 4, tx = tid & 15;
    // Phase A: masked decayed scores sc[i][j] = exp(cum_i - cum_j) * dot(C_i, B_j)
    {
        float acc[8][8];
        #pragma unroll
        for (int r = 0; r < 8; r++)
            #pragma unroll
            for (int s = 0; s < 8; s++) acc[r][s] = 0.f;
        int i0 = ty * 8;
        for (int n = 0; n < DSTATE; n++) {
            float cf[8], bf[8];
            #pragma unroll
            for (int r = 0; r < 8; r++) cf[r] = Cs[(i0 + r) * 65 + n];
            #pragma unroll
            for (int s = 0; s < 8; s++) bf[s] = Bs[(tx + 16 * s) * 65 + n];
            #pragma unroll
            for (int r = 0; r < 8; r++)
                #pragma unroll
                for (int s = 0; s < 8; s++) acc[r][s] += cf[r] * bf[s];
        }
        #pragma unroll
        for (int r = 0; r < 8; r++) {
            int i = i0 + r;
            float ci = cum[i];
            #pragma unroll
            for (int s = 0; s < 8; s++) {
                int j = tx + 16 * s;
                sc[i * 129 + j] = (j <= i) ? expf(ci - cum[j]) * acc[r][s] : 0.f;
            }
        }
    }
    __syncthreads();
    // Phase B: y_intra = sc @ x
    {
        float acc[8][4];
        #pragma unroll
        for (int r = 0; r < 8; r++)
            #pragma unroll
            for (int cc = 0; cc < 4; cc++) acc[r][cc] = 0.f;
        int i0 = ty * 8, p0 = tx * 4;
        for (int j = 0; j < CHUNK; j++) {
            float xv[4];
            #pragma unroll
            for (int cc = 0; cc < 4; cc++) xv[cc] = xs[j * 65 + p0 + cc];
            #pragma unroll
            for (int r = 0; r < 8; r++) {
                float sf = sc[(i0 + r) * 129 + j];
                #pragma unroll
                for (int cc = 0; cc < 4; cc++) acc[r][cc] += sf * xv[cc];
            }
        }
        #pragma unroll
        for (int r = 0; r < 8; r++) {
            size_t ybase = (size_t)(m0 + i0 + r) * DINNER + h * HD + p0;
            #pragma unroll
            for (int cc = 0; cc < 4; cc++) y[ybase + cc] = acc[r][cc];
        }
    }
    // Phase C: chunk state S[n][p] = sum_j dend[j] * B[j,n] * x[j,p]
    {
        int n = tid >> 2;
        int p0 = (tid & 3) * 16;
        float acc[16];
        #pragma unroll
        for (int cc = 0; cc < 16; cc++) acc[cc] = 0.f;
        for (int j = 0; j < CHUNK; j++) {
            float w = dend[j] * Bs[j * 65 + n];
            #pragma unroll
            for (int cc = 0; cc < 16; cc++) acc[cc] += w * xs[j * 65 + p0 + cc];
        }
        size_t off = ((size_t)((b * NCHUNK + c) * NH + h)) * (DSTATE * HD) + n * HD + p0;
        #pragma unroll
        for (int cc = 0; cc < 16; cc++) Sg[off + cc] = acc[cc];
        if (tid == 0) Ag[(b * NCHUNK + c) * NH + h] = expf(cum[CHUNK - 1]);
    }
    if (tid < CHUNK)
        cumg[((size_t)((b * NCHUNK + c) * NH + h)) * CHUNK + tid] = cum[tid];
}

// ------------------------------ inter-chunk state recurrence ----------------
__global__ void state_scan_kernel(const float* __restrict__ Sg, const float* __restrict__ Ag,
                                  float* __restrict__ Hp) {
    int b = blockIdx.x / NH, h = blockIdx.x % NH;
    int tid = threadIdx.x;
    float H[16];
    #pragma unroll
    for (int k = 0; k < 16; k++) H[k] = 0.f;
    for (int c = 0; c < NCHUNK; c++) {
        size_t off = ((size_t)((b * NCHUNK + c) * NH + h)) * (DSTATE * HD);
        float Ac = Ag[(b * NCHUNK + c) * NH + h];
        #pragma unroll
        for (int k = 0; k < 16; k++) {
            int e = tid + k * 256;
            Hp[off + e] = H[k];
            H[k] = Ac * H[k] + Sg[off + e];
        }
    }
}

// ------------------------------ y_inter + D*x + gating ---------------------
__global__ void y_inter_kernel(const float* __restrict__ zx, const float* __restrict__ xBC,
                               const float* __restrict__ Hp, const float* __restrict__ cumg,
                               const float* __restrict__ Dvec, const float* __restrict__ zb,
                               float* __restrict__ y) {
    extern __shared__ float sm[];
    float* Cs  = sm;                  // 128*65
    float* xs  = Cs + CHUNK * 65;     // 128*65
    float* Hs  = xs + CHUNK * 65;     // 64*65
    float* cum = Hs + DSTATE * 65;    // 128

    int h = blockIdx.x % NH;
    int c = (blockIdx.x / NH) % NCHUNK;
    int b = blockIdx.x / (NH * NCHUNK);
    int tid = threadIdx.x;
    int m0 = b * LSEQ + c * CHUNK;
    size_t hoff = (size_t)((b * NCHUNK + c) * NH + h);

    for (int idx = tid; idx < CHUNK * HD; idx += 256) {
        int i = idx >> 6, p = idx & 63;
        size_t rowb = (size_t)(m0 + i) * CONVD;
        xs[i * 65 + p] = xBC[rowb + h * HD + p];
        Cs[i * 65 + p] = xBC[rowb + DINNER + NH * DSTATE + h * DSTATE + p];
    }
    for (int idx = tid; idx < DSTATE * HD; idx += 256)
        Hs[(idx >> 6) * 65 + (idx & 63)] = Hp[hoff * (DSTATE * HD) + idx];
    if (tid < CHUNK) cum[tid] = cumg[hoff * CHUNK + tid];
    __syncthreads();

    int i = tid >> 1;
    int p0 = (tid & 1) * 32;
    float acc[32];
    #pragma unroll
    for (int cc = 0; cc < 32; cc++) acc[cc] = 0.f;
    for (int n = 0; n < DSTATE; n++) {
        float cv = Cs[i * 65 + n];
        #pragma unroll
        for (int cc = 0; cc < 32; cc++) acc[cc] += cv * Hs[n * 65 + p0 + cc];
    }
    float e = expf(cum[i]);
    float Dh = Dvec[h];
    int m = m0 + i;
    size_t ybase = (size_t)m * DINNER + h * HD;
    size_t zbase = (size_t)m * DINPROJ + h * HD;
    #pragma unroll
    for (int cc = 0; cc < 32; cc++) {
        int p = p0 + cc;
        float yt = y[ybase + p] + e * acc[cc] + Dh * xs[i * 65 + p];
        float g = zx[zbase + p] + zb[h * HD + p];
        float sg = g / (1.f + expf(-g));
        y[ybase + p] = yt * sg;
    }
}

// ------------------------------ MLP elementwise -----------------------------
__global__ void silu_mul_kernel(float* __restrict__ gate, const float* __restrict__ up,
                                size_t n) {
    size_t i = (size_t)blockIdx.x * blockDim.x + threadIdx.x;
    if (i < n) {
        float g = gate[i];
        gate[i] = (g / (1.f + expf(-g))) * up[i];
    }
}

// ------------------------------ launch --------------------------------------
extern "C" void kernel_launch(void* const* d_in, const int* in_sizes, int n_in,
                              void* d_out, int out_size) {
    const float* hidden     = (const float*)d_in[0];
    const float* in_proj_w  = (const float*)d_in[1];
    const float* z_bias     = (const float*)d_in[2];
    const float* conv_w     = (const float*)d_in[3];
    const float* conv_b     = (const float*)d_in[4];
    const float* Dvec       = (const float*)d_in[5];
    const float* out_proj_w = (const float*)d_in[6];
    const float* norm1_w    = (const float*)d_in[7];
    const float* norm2_w    = (const float*)d_in[8];
    const float* gate_w     = (const float*)d_in[9];
    const float* up_w       = (const float*)d_in[10];
    const float* down_w     = (const float*)d_in[11];
    float* out = (float*)d_out;

    float *h1, *zx, *xbc, *y, *S, *A, *cumg, *Hp, *h2, *h3, *gate, *up;
    cudaGetSymbolAddress((void**)&h1,   g_h1);
    cudaGetSymbolAddress((void**)&zx,   g_zx);
    cudaGetSymbolAddress((void**)&xbc,  g_xBC);
    cudaGetSymbolAddress((void**)&y,    g_y);
    cudaGetSymbolAddress((void**)&S,    g_S);
    cudaGetSymbolAddress((void**)&A,    g_Ac);
    cudaGetSymbolAddress((void**)&cumg, g_cum);
    cudaGetSymbolAddress((void**)&Hp,   g_Hp);
    cudaGetSymbolAddress((void**)&h2,   g_h2);
    cudaGetSymbolAddress((void**)&h3,   g_h3);
    cudaGetSymbolAddress((void**)&gate, g_gate);
    cudaGetSymbolAddress((void**)&up,   g_up);

    const int SMEM_INTRA  = (3 * CHUNK * 65 + CHUNK * 129 + 2 * CHUNK) * sizeof(float);
    const int SMEM_YINTER = (2 * CHUNK * 65 + DSTATE * 65 + CHUNK) * sizeof(float);
    cudaFuncSetAttribute(ssd_intra_kernel, cudaFuncAttributeMaxDynamicSharedMemorySize, SMEM_INTRA);
    cudaFuncSetAttribute(y_inter_kernel,  cudaFuncAttributeMaxDynamicSharedMemorySize, SMEM_YINTER);

    // 1) rmsnorm 1
    rmsnorm_kernel<<<MTOK, 256>>>(hidden, norm1_w, h1);
    // 2) in_proj: zx = h1 @ in_proj_w^T   [4096 x 8224]
    sgemm_nt_kernel<<<dim3((DINPROJ + 127) / 128, MTOK / 128), 256>>>(
        h1, in_proj_w, nullptr, zx, MTOK, DINPROJ, DMODEL);
    // 3) causal depthwise conv over xBC slice
    conv1d_kernel<<<(int)(((size_t)MTOK * CONVD + 255) / 256), 256>>>(zx, conv_w, conv_b, xbc);
    // 4) SSD intra-chunk (y_intra, S, A, cum)
    ssd_intra_kernel<<<BATCH * NCHUNK * NH, 256, SMEM_INTRA>>>(zx, xbc, y, S, A, cumg);
    // 5) inter-chunk state recurrence
    state_scan_kernel<<<BATCH * NH, 256>>>(S, A, Hp);
    // 6) y_inter + D*x + silu(z) gating (in-place on y)
    y_inter_kernel<<<BATCH * NCHUNK * NH, 256, SMEM_YINTER>>>(zx, xbc, Hp, cumg, Dvec, z_bias, y);
    // 7) out_proj + residual: h2 = y @ out_proj_w^T + hidden
    sgemm_nt_kernel<<<dim3(DMODEL / 128, MTOK / 128), 256>>>(
        y, out_proj_w, hidden, h2, MTOK, DMODEL, DINNER);
    // 8) rmsnorm 2
    rmsnorm_kernel<<<MTOK, 256>>>(h2, norm2_w, h3);
    // 9) MLP gate / up
    sgemm_nt_kernel<<<dim3(DFF / 128, MTOK / 128), 256>>>(
        h3, gate_w, nullptr, gate, MTOK, DFF, DMODEL);
    sgemm_nt_kernel<<<dim3(DFF / 128, MTOK / 128), 256>>>(
        h3, up_w, nullptr, up, MTOK, DFF, DMODEL);
    // 10) act = silu(gate) * up (in-place on gate)
    silu_mul_kernel<<<(int)(((size_t)MTOK * DFF + 255) / 256), 256>>>(
        gate, up, (size_t)MTOK * DFF);
    // 11) down + residual: out = act @ down_w^T + h2
    sgemm_nt_kernel<<<dim3(DMODEL / 128, MTOK / 128), 256>>>(
        gate, down_w, h2, out, MTOK, DMODEL, DFF);
}